// round 14
// baseline (speedup 1.0000x reference)
#include <cuda_runtime.h>
#include <cstdint>

#define D 128

// 3 rows per warp: the untested middle cell of the rows-per-warp sweep.
// ~100 regs -> 10 blocks/SM at 64-thr blocks = 20 warps/SM, 360 in-flight
// gathers/SM (max so far), epilogue amortized over 3 rows.
__global__ __launch_bounds__(64) void sgns_kernel14(
    const int*   __restrict__ x,        // [BS, 1, 3] int32
    const float* __restrict__ tgt_base,
    const float* __restrict__ tgt_a,
    const float* __restrict__ tgt_b,
    const float* __restrict__ ctx_base,
    const float* __restrict__ ctx_a,
    const float* __restrict__ ctx_b,
    const float* __restrict__ tgt_w,    // [3,1]
    const float* __restrict__ ctx_w,    // [3,1]
    float*       __restrict__ out,      // [BS]
    int bs)
{
    const int warp = (blockIdx.x * blockDim.x + threadIdx.x) >> 5;
    const int lane = threadIdx.x & 31;
    const int r0 = warp * 3;
    if (r0 >= bs) return;

    const bool h1 = (r0 + 1 < bs);
    const bool h2 = (r0 + 2 < bs);

    // 9 indices for 3 rows. 36B per warp — scalar loads (alignment-safe).
    int idx[3][3];
    #pragma unroll
    for (int k = 0; k < 3; k++) idx[0][k] = __ldg(&x[(size_t)r0 * 3 + k]);
    #pragma unroll
    for (int k = 0; k < 3; k++) idx[1][k] = h1 ? __ldg(&x[(size_t)(r0 + 1) * 3 + k]) : idx[0][k];
    #pragma unroll
    for (int k = 0; k < 3; k++) idx[2][k] = h2 ? __ldg(&x[(size_t)(r0 + 2) * 3 + k]) : idx[0][k];

    // 18 independent 16B gathers, all issued before dependent math
    float4 tb[3], ta[3], tc[3], cb[3], ca[3], cc[3];
    #pragma unroll
    for (int r = 0; r < 3; r++) {
        tb[r] = __ldg((const float4*)(tgt_base + (size_t)idx[r][0] * D) + lane);
        ta[r] = __ldg((const float4*)(tgt_a    + (size_t)idx[r][1] * D) + lane);
        tc[r] = __ldg((const float4*)(tgt_b    + (size_t)idx[r][2] * D) + lane);
        cb[r] = __ldg((const float4*)(ctx_base + (size_t)idx[r][0] * D) + lane);
        ca[r] = __ldg((const float4*)(ctx_a    + (size_t)idx[r][1] * D) + lane);
        cc[r] = __ldg((const float4*)(ctx_b    + (size_t)idx[r][2] * D) + lane);
    }

    // softmax weights — overlap with gather latency
    float tw0 = __ldg(&tgt_w[0]), tw1 = __ldg(&tgt_w[1]), tw2 = __ldg(&tgt_w[2]);
    float tm  = fmaxf(tw0, fmaxf(tw1, tw2));
    float te0 = expf(tw0 - tm), te1 = expf(tw1 - tm), te2 = expf(tw2 - tm);
    float ti  = 1.0f / (te0 + te1 + te2);
    const float w0 = te0 * ti, w1 = te1 * ti, w2 = te2 * ti;

    float cw0 = __ldg(&ctx_w[0]), cw1 = __ldg(&ctx_w[1]), cw2 = __ldg(&ctx_w[2]);
    float cm  = fmaxf(cw0, fmaxf(cw1, cw2));
    float ce0 = expf(cw0 - cm), ce1 = expf(cw1 - cm), ce2 = expf(cw2 - cm);
    float ci  = 1.0f / (ce0 + ce1 + ce2);
    const float v0 = ce0 * ci, v1 = ce1 * ci, v2 = ce2 * ci;

    float p[3];
    #pragma unroll
    for (int r = 0; r < 3; r++) {
        float tx, cx, acc;
        tx  = w0 * tb[r].x + w1 * ta[r].x + w2 * tc[r].x;
        cx  = v0 * cb[r].x + v1 * ca[r].x + v2 * cc[r].x;
        acc = tx * cx;
        tx  = w0 * tb[r].y + w1 * ta[r].y + w2 * tc[r].y;
        cx  = v0 * cb[r].y + v1 * ca[r].y + v2 * cc[r].y;
        acc += tx * cx;
        tx  = w0 * tb[r].z + w1 * ta[r].z + w2 * tc[r].z;
        cx  = v0 * cb[r].z + v1 * ca[r].z + v2 * cc[r].z;
        acc += tx * cx;
        tx  = w0 * tb[r].w + w1 * ta[r].w + w2 * tc[r].w;
        cx  = v0 * cb[r].w + v1 * ca[r].w + v2 * cc[r].w;
        acc += tx * cx;
        p[r] = acc;
    }

    // 3 reduction chains pipeline through the SHFL latency
    #pragma unroll
    for (int off = 16; off > 0; off >>= 1) {
        #pragma unroll
        for (int r = 0; r < 3; r++)
            p[r] += __shfl_xor_sync(0xFFFFFFFFu, p[r], off);
    }

    if (lane == 0) {
        out[r0] = 1.0f / (1.0f + expf(-p[0]));
        if (h1) out[r0 + 1] = 1.0f / (1.0f + expf(-p[1]));
        if (h2) out[r0 + 2] = 1.0f / (1.0f + expf(-p[2]));
    }
}

extern "C" void kernel_launch(void* const* d_in, const int* in_sizes, int n_in,
                              void* d_out, int out_size)
{
    const int*   x        = (const int*)  d_in[0];
    const float* tgt_base = (const float*)d_in[1];
    const float* tgt_a    = (const float*)d_in[2];
    const float* tgt_b    = (const float*)d_in[3];
    const float* ctx_base = (const float*)d_in[4];
    const float* ctx_a    = (const float*)d_in[5];
    const float* ctx_b    = (const float*)d_in[6];
    const float* tgt_w    = (const float*)d_in[7];
    const float* ctx_w    = (const float*)d_in[8];
    float* out = (float*)d_out;

    const int bs = in_sizes[0] / 3;
    const int threads = 64;                        // 2 warps/block
    const int rows_per_block = (threads / 32) * 3; // 6 rows/block
    const int blocks = (bs + rows_per_block - 1) / rows_per_block;

    sgns_kernel14<<<blocks, threads>>>(x, tgt_base, tgt_a, tgt_b,
                                       ctx_base, ctx_a, ctx_b,
                                       tgt_w, ctx_w, out, bs);
}

// round 15
// speedup vs baseline: 1.0239x; 1.0239x over previous
#include <cuda_runtime.h>
#include <cstdint>

#define D 128

union V32 { unsigned long long u[4]; float f[8]; };

// 256-bit non-coherent load with L2::evict_last (only legal width on sm_103).
__device__ __forceinline__ V32 ldg256_el(const float* p)
{
    V32 v;
    asm volatile("ld.global.nc.L2::evict_last.v4.b64 {%0,%1,%2,%3}, [%4];"
                 : "=l"(v.u[0]), "=l"(v.u[1]), "=l"(v.u[2]), "=l"(v.u[3])
                 : "l"(p));
    return v;
}

// Champion block shape (r2: 256 thr, best measured 8.672us) fused with the
// r9b 256-bit/evict_last gather body (6 LDG.256 per warp, half-warp per row).
__global__ __launch_bounds__(256) void sgns_kernel15(
    const int*   __restrict__ x,        // [BS, 1, 3] int32
    const float* __restrict__ tgt_base,
    const float* __restrict__ tgt_a,
    const float* __restrict__ tgt_b,
    const float* __restrict__ ctx_base,
    const float* __restrict__ ctx_a,
    const float* __restrict__ ctx_b,
    const float* __restrict__ tgt_w,    // [3,1]
    const float* __restrict__ ctx_w,    // [3,1]
    float*       __restrict__ out,      // [BS]
    int bs)
{
    const int warp = (blockIdx.x * blockDim.x + threadIdx.x) >> 5;
    const int lane = threadIdx.x & 31;
    const int half = lane >> 4;          // 0: row r0, 1: row r1
    const int sub  = lane & 15;          // 16 lanes x 8 floats = 128 dims
    const int r0 = warp * 2;
    if (r0 >= bs) return;
    const bool has_r1 = (r0 + 1 < bs);

    // 6 indices as 3x int2; each half-warp takes its row's triple
    const int2* xp = (const int2*)(x + (size_t)warp * 6);
    const int2 xa = __ldg(xp + 0);
    const int2 xb = __ldg(xp + 1);
    const int2 xc = __ldg(xp + 2);
    int i0, i1, i2;
    if (half == 0 || !has_r1) { i0 = xa.x; i1 = xa.y; i2 = xb.x; }
    else                      { i0 = xb.y; i1 = xc.x; i2 = xc.y; }

    // 6 LDG.256 per warp, each covering both rows (one per half-warp)
    const int off = sub * 8;
    V32 tb = ldg256_el(tgt_base + (size_t)i0 * D + off);
    V32 ta = ldg256_el(tgt_a    + (size_t)i1 * D + off);
    V32 tc = ldg256_el(tgt_b    + (size_t)i2 * D + off);
    V32 cb = ldg256_el(ctx_base + (size_t)i0 * D + off);
    V32 ca = ldg256_el(ctx_a    + (size_t)i1 * D + off);
    V32 cc = ldg256_el(ctx_b    + (size_t)i2 * D + off);

    // softmax weights — overlap with gather latency
    float tw0 = __ldg(&tgt_w[0]), tw1 = __ldg(&tgt_w[1]), tw2 = __ldg(&tgt_w[2]);
    float tm  = fmaxf(tw0, fmaxf(tw1, tw2));
    float te0 = __expf(tw0 - tm), te1 = __expf(tw1 - tm), te2 = __expf(tw2 - tm);
    float ti  = __frcp_rn(te0 + te1 + te2);
    const float w0 = te0 * ti, w1 = te1 * ti, w2 = te2 * ti;

    float cw0 = __ldg(&ctx_w[0]), cw1 = __ldg(&ctx_w[1]), cw2 = __ldg(&ctx_w[2]);
    float cm  = fmaxf(cw0, fmaxf(cw1, cw2));
    float ce0 = __expf(cw0 - cm), ce1 = __expf(cw1 - cm), ce2 = __expf(cw2 - cm);
    float ci  = __frcp_rn(ce0 + ce1 + ce2);
    const float v0 = ce0 * ci, v1 = ce1 * ci, v2 = ce2 * ci;

    // per-lane partial dot over 8 dims
    float p = 0.0f;
    #pragma unroll
    for (int j = 0; j < 8; j++) {
        float t = w0 * tb.f[j] + w1 * ta.f[j] + w2 * tc.f[j];
        float c = v0 * cb.f[j] + v1 * ca.f[j] + v2 * cc.f[j];
        p += t * c;
    }

    // reduce within each 16-lane half
    #pragma unroll
    for (int o = 8; o > 0; o >>= 1)
        p += __shfl_xor_sync(0xFFFFFFFFu, p, o);

    // swap halves so lane 0 holds both rows' sums
    float q = __shfl_xor_sync(0xFFFFFFFFu, p, 16);

    if (lane == 0) {
        float s0 = __frcp_rn(1.0f + __expf(-p));
        float s1 = __frcp_rn(1.0f + __expf(-q));
        if (has_r1) {
            *(float2*)(out + r0) = make_float2(s0, s1);
        } else {
            out[r0] = s0;
        }
    }
}

extern "C" void kernel_launch(void* const* d_in, const int* in_sizes, int n_in,
                              void* d_out, int out_size)
{
    const int*   x        = (const int*)  d_in[0];
    const float* tgt_base = (const float*)d_in[1];
    const float* tgt_a    = (const float*)d_in[2];
    const float* tgt_b    = (const float*)d_in[3];
    const float* ctx_base = (const float*)d_in[4];
    const float* ctx_a    = (const float*)d_in[5];
    const float* ctx_b    = (const float*)d_in[6];
    const float* tgt_w    = (const float*)d_in[7];
    const float* ctx_w    = (const float*)d_in[8];
    float* out = (float*)d_out;

    const int bs = in_sizes[0] / 3;
    const int threads = 256;                 // champion block size (r2)
    const int rows_per_block = (threads / 32) * 2;
    const int blocks = (bs + rows_per_block - 1) / rows_per_block;

    sgns_kernel15<<<blocks, threads>>>(x, tgt_base, tgt_a, tgt_b,
                                       ctx_base, ctx_a, ctx_b,
                                       tgt_w, ctx_w, out, bs);
}

// round 16
// speedup vs baseline: 1.1787x; 1.1512x over previous
#include <cuda_runtime.h>
#include <cuda_bf16.h>

#ifndef D
#define D 128
#endif

// FINAL champion — byte-identical to the round-2/round-13 winner.
// Measured 8.672us (r2) and 8.704us (r13): the only binary reproduced fast 2/2.
//
// Structure: 256-thr blocks, one 2-row task per warp, 12 independent LDG.128
// gathers issued before any dependent math (MLP=12), dual pipelined shuffle
// reductions, float2 epilogue store.
//
// 15 rounds of evidence: bound by the memory system's service rate for random
// 512B embedding rows (~5.5 TB/s warm, DRAM 42-48% / issue <=26% cold-ncu).
// Eliminated alternatives: 1/3/4 rows per warp, 64/128-thr blocks, reg caps
// (spills), register double-buffering, cp.async smem pipelines, persistent
// single-wave shapes, LDG.256, L2::evict_last hints, MUFU epilogue — all
// measured equal (8.7) or worse (10.2-13.0).
__global__ __launch_bounds__(256) void sgns_kernel2(
    const int*   __restrict__ x,        // [BS, 1, 3] int32
    const float* __restrict__ tgt_base, // [VOCAB, 128]
    const float* __restrict__ tgt_a,    // [SIDE, 128]
    const float* __restrict__ tgt_b,    // [SIDE, 128]
    const float* __restrict__ ctx_base, // [VOCAB, 128]
    const float* __restrict__ ctx_a,    // [SIDE, 128]
    const float* __restrict__ ctx_b,    // [SIDE, 128]
    const float* __restrict__ tgt_w,    // [3,1]
    const float* __restrict__ ctx_w,    // [3,1]
    float*       __restrict__ out,      // [BS]
    int bs)
{
    const int warp = (blockIdx.x * blockDim.x + threadIdx.x) >> 5;
    const int lane = threadIdx.x & 31;
    const int r0 = warp * 2;
    const int r1 = r0 + 1;
    if (r0 >= bs) return;
    const bool has_r1 = (r1 < bs);

    // indices for both rows (broadcast loads, L2/L1 resident)
    const int a0 = __ldg(&x[r0 * 3 + 0]);
    const int a1 = __ldg(&x[r0 * 3 + 1]);
    const int a2 = __ldg(&x[r0 * 3 + 2]);
    const int b0 = has_r1 ? __ldg(&x[r1 * 3 + 0]) : a0;
    const int b1 = has_r1 ? __ldg(&x[r1 * 3 + 1]) : a1;
    const int b2 = has_r1 ? __ldg(&x[r1 * 3 + 2]) : a2;

    // 12 independent gathers — issue all before any dependent math (MLP=12)
    const float4 t0b = __ldg((const float4*)(tgt_base + (size_t)a0 * D) + lane);
    const float4 t0a = __ldg((const float4*)(tgt_a    + (size_t)a1 * D) + lane);
    const float4 t0c = __ldg((const float4*)(tgt_b    + (size_t)a2 * D) + lane);
    const float4 c0b = __ldg((const float4*)(ctx_base + (size_t)a0 * D) + lane);
    const float4 c0a = __ldg((const float4*)(ctx_a    + (size_t)a1 * D) + lane);
    const float4 c0c = __ldg((const float4*)(ctx_b    + (size_t)a2 * D) + lane);

    const float4 t1b = __ldg((const float4*)(tgt_base + (size_t)b0 * D) + lane);
    const float4 t1a = __ldg((const float4*)(tgt_a    + (size_t)b1 * D) + lane);
    const float4 t1c = __ldg((const float4*)(tgt_b    + (size_t)b2 * D) + lane);
    const float4 c1b = __ldg((const float4*)(ctx_base + (size_t)b0 * D) + lane);
    const float4 c1a = __ldg((const float4*)(ctx_a    + (size_t)b1 * D) + lane);
    const float4 c1c = __ldg((const float4*)(ctx_b    + (size_t)b2 * D) + lane);

    // softmax(tgt_w), softmax(ctx_w) — overlaps with gather latency
    float tw0 = __ldg(&tgt_w[0]), tw1 = __ldg(&tgt_w[1]), tw2 = __ldg(&tgt_w[2]);
    float tm  = fmaxf(tw0, fmaxf(tw1, tw2));
    float te0 = expf(tw0 - tm), te1 = expf(tw1 - tm), te2 = expf(tw2 - tm);
    float tinv = 1.0f / (te0 + te1 + te2);
    float w0 = te0 * tinv, w1 = te1 * tinv, w2 = te2 * tinv;

    float cw0 = __ldg(&ctx_w[0]), cw1 = __ldg(&ctx_w[1]), cw2 = __ldg(&ctx_w[2]);
    float cm  = fmaxf(cw0, fmaxf(cw1, cw2));
    float ce0 = expf(cw0 - cm), ce1 = expf(cw1 - cm), ce2 = expf(cw2 - cm);
    float cinv = 1.0f / (ce0 + ce1 + ce2);
    float v0 = ce0 * cinv, v1 = ce1 * cinv, v2 = ce2 * cinv;

    // row 0 dot contribution
    float tx, cx, p0, p1;
    tx = w0 * t0b.x + w1 * t0a.x + w2 * t0c.x;
    cx = v0 * c0b.x + v1 * c0a.x + v2 * c0c.x;
    p0 = tx * cx;
    tx = w0 * t0b.y + w1 * t0a.y + w2 * t0c.y;
    cx = v0 * c0b.y + v1 * c0a.y + v2 * c0c.y;
    p0 += tx * cx;
    tx = w0 * t0b.z + w1 * t0a.z + w2 * t0c.z;
    cx = v0 * c0b.z + v1 * c0a.z + v2 * c0c.z;
    p0 += tx * cx;
    tx = w0 * t0b.w + w1 * t0a.w + w2 * t0c.w;
    cx = v0 * c0b.w + v1 * c0a.w + v2 * c0c.w;
    p0 += tx * cx;

    // row 1 dot contribution
    tx = w0 * t1b.x + w1 * t1a.x + w2 * t1c.x;
    cx = v0 * c1b.x + v1 * c1a.x + v2 * c1c.x;
    p1 = tx * cx;
    tx = w0 * t1b.y + w1 * t1a.y + w2 * t1c.y;
    cx = v0 * c1b.y + v1 * c1a.y + v2 * c1c.y;
    p1 += tx * cx;
    tx = w0 * t1b.z + w1 * t1a.z + w2 * t1c.z;
    cx = v0 * c1b.z + v1 * c1a.z + v2 * c1c.z;
    p1 += tx * cx;
    tx = w0 * t1b.w + w1 * t1a.w + w2 * t1c.w;
    cx = v0 * c1b.w + v1 * c1a.w + v2 * c1c.w;
    p1 += tx * cx;

    // warp reduction — the two chains interleave/pipeline
    #pragma unroll
    for (int off = 16; off > 0; off >>= 1) {
        p0 += __shfl_xor_sync(0xFFFFFFFFu, p0, off);
        p1 += __shfl_xor_sync(0xFFFFFFFFu, p1, off);
    }

    if (lane == 0) {
        float s0 = 1.0f / (1.0f + expf(-p0));
        float s1 = 1.0f / (1.0f + expf(-p1));
        if (has_r1) {
            *(float2*)(out + r0) = make_float2(s0, s1);  // r0 even -> 8B aligned
        } else {
            out[r0] = s0;
        }
    }
}

extern "C" void kernel_launch(void* const* d_in, const int* in_sizes, int n_in,
                              void* d_out, int out_size)
{
    const int*   x        = (const int*)  d_in[0];
    const float* tgt_base = (const float*)d_in[1];
    const float* tgt_a    = (const float*)d_in[2];
    const float* tgt_b    = (const float*)d_in[3];
    const float* ctx_base = (const float*)d_in[4];
    const float* ctx_a    = (const float*)d_in[5];
    const float* ctx_b    = (const float*)d_in[6];
    const float* tgt_w    = (const float*)d_in[7];
    const float* ctx_w    = (const float*)d_in[8];
    float* out = (float*)d_out;

    const int bs = in_sizes[0] / 3;
    const int rows_per_warp = 2;
    const int threads = 256;
    const int warps_per_block = threads / 32;
    const int rows_per_block = warps_per_block * rows_per_warp;
    const int blocks = (bs + rows_per_block - 1) / rows_per_block;

    sgns_kernel2<<<blocks, threads>>>(x, tgt_base, tgt_a, tgt_b,
                                      ctx_base, ctx_a, ctx_b,
                                      tgt_w, ctx_w, out, bs);
}

// round 17
// speedup vs baseline: 1.2250x; 1.0393x over previous
#include <cuda_runtime.h>
#include <cuda_bf16.h>

#ifndef D
#define D 128
#endif

// FINAL champion — byte-identical to the r2/r13/r16 binary.
// A/A samples: 8.672 / 8.704 / 9.312 us. Every structural variant measured
// slower (10.2-13.0): 1/3/4 rows per warp, 64/128-thr blocks, reg caps,
// register double-buffering, cp.async smem pipelines, persistent single-wave,
// LDG.256, L2::evict_last, MUFU epilogue.
//
// Bound: memory-system service rate for random 512B embedding rows
// (~5.5 TB/s warm; cold-ncu DRAM ~47%, issue ~26%, all pipes <50%).
__global__ __launch_bounds__(256) void sgns_kernel2(
    const int*   __restrict__ x,        // [BS, 1, 3] int32
    const float* __restrict__ tgt_base, // [VOCAB, 128]
    const float* __restrict__ tgt_a,    // [SIDE, 128]
    const float* __restrict__ tgt_b,    // [SIDE, 128]
    const float* __restrict__ ctx_base, // [VOCAB, 128]
    const float* __restrict__ ctx_a,    // [SIDE, 128]
    const float* __restrict__ ctx_b,    // [SIDE, 128]
    const float* __restrict__ tgt_w,    // [3,1]
    const float* __restrict__ ctx_w,    // [3,1]
    float*       __restrict__ out,      // [BS]
    int bs)
{
    const int warp = (blockIdx.x * blockDim.x + threadIdx.x) >> 5;
    const int lane = threadIdx.x & 31;
    const int r0 = warp * 2;
    const int r1 = r0 + 1;
    if (r0 >= bs) return;
    const bool has_r1 = (r1 < bs);

    // indices for both rows (broadcast loads, L2/L1 resident)
    const int a0 = __ldg(&x[r0 * 3 + 0]);
    const int a1 = __ldg(&x[r0 * 3 + 1]);
    const int a2 = __ldg(&x[r0 * 3 + 2]);
    const int b0 = has_r1 ? __ldg(&x[r1 * 3 + 0]) : a0;
    const int b1 = has_r1 ? __ldg(&x[r1 * 3 + 1]) : a1;
    const int b2 = has_r1 ? __ldg(&x[r1 * 3 + 2]) : a2;

    // 12 independent gathers — issue all before any dependent math (MLP=12)
    const float4 t0b = __ldg((const float4*)(tgt_base + (size_t)a0 * D) + lane);
    const float4 t0a = __ldg((const float4*)(tgt_a    + (size_t)a1 * D) + lane);
    const float4 t0c = __ldg((const float4*)(tgt_b    + (size_t)a2 * D) + lane);
    const float4 c0b = __ldg((const float4*)(ctx_base + (size_t)a0 * D) + lane);
    const float4 c0a = __ldg((const float4*)(ctx_a    + (size_t)a1 * D) + lane);
    const float4 c0c = __ldg((const float4*)(ctx_b    + (size_t)a2 * D) + lane);

    const float4 t1b = __ldg((const float4*)(tgt_base + (size_t)b0 * D) + lane);
    const float4 t1a = __ldg((const float4*)(tgt_a    + (size_t)b1 * D) + lane);
    const float4 t1c = __ldg((const float4*)(tgt_b    + (size_t)b2 * D) + lane);
    const float4 c1b = __ldg((const float4*)(ctx_base + (size_t)b0 * D) + lane);
    const float4 c1a = __ldg((const float4*)(ctx_a    + (size_t)b1 * D) + lane);
    const float4 c1c = __ldg((const float4*)(ctx_b    + (size_t)b2 * D) + lane);

    // softmax(tgt_w), softmax(ctx_w) — overlaps with gather latency
    float tw0 = __ldg(&tgt_w[0]), tw1 = __ldg(&tgt_w[1]), tw2 = __ldg(&tgt_w[2]);
    float tm  = fmaxf(tw0, fmaxf(tw1, tw2));
    float te0 = expf(tw0 - tm), te1 = expf(tw1 - tm), te2 = expf(tw2 - tm);
    float tinv = 1.0f / (te0 + te1 + te2);
    float w0 = te0 * tinv, w1 = te1 * tinv, w2 = te2 * tinv;

    float cw0 = __ldg(&ctx_w[0]), cw1 = __ldg(&ctx_w[1]), cw2 = __ldg(&ctx_w[2]);
    float cm  = fmaxf(cw0, fmaxf(cw1, cw2));
    float ce0 = expf(cw0 - cm), ce1 = expf(cw1 - cm), ce2 = expf(cw2 - cm);
    float cinv = 1.0f / (ce0 + ce1 + ce2);
    float v0 = ce0 * cinv, v1 = ce1 * cinv, v2 = ce2 * cinv;

    // row 0 dot contribution
    float tx, cx, p0, p1;
    tx = w0 * t0b.x + w1 * t0a.x + w2 * t0c.x;
    cx = v0 * c0b.x + v1 * c0a.x + v2 * c0c.x;
    p0 = tx * cx;
    tx = w0 * t0b.y + w1 * t0a.y + w2 * t0c.y;
    cx = v0 * c0b.y + v1 * c0a.y + v2 * c0c.y;
    p0 += tx * cx;
    tx = w0 * t0b.z + w1 * t0a.z + w2 * t0c.z;
    cx = v0 * c0b.z + v1 * c0a.z + v2 * c0c.z;
    p0 += tx * cx;
    tx = w0 * t0b.w + w1 * t0a.w + w2 * t0c.w;
    cx = v0 * c0b.w + v1 * c0a.w + v2 * c0c.w;
    p0 += tx * cx;

    // row 1 dot contribution
    tx = w0 * t1b.x + w1 * t1a.x + w2 * t1c.x;
    cx = v0 * c1b.x + v1 * c1a.x + v2 * c1c.x;
    p1 = tx * cx;
    tx = w0 * t1b.y + w1 * t1a.y + w2 * t1c.y;
    cx = v0 * c1b.y + v1 * c1a.y + v2 * c1c.y;
    p1 += tx * cx;
    tx = w0 * t1b.z + w1 * t1a.z + w2 * t1c.z;
    cx = v0 * c1b.z + v1 * c1a.z + v2 * c1c.z;
    p1 += tx * cx;
    tx = w0 * t1b.w + w1 * t1a.w + w2 * t1c.w;
    cx = v0 * c1b.w + v1 * c1a.w + v2 * c1c.w;
    p1 += tx * cx;

    // warp reduction — the two chains interleave/pipeline
    #pragma unroll
    for (int off = 16; off > 0; off >>= 1) {
        p0 += __shfl_xor_sync(0xFFFFFFFFu, p0, off);
        p1 += __shfl_xor_sync(0xFFFFFFFFu, p1, off);
    }

    if (lane == 0) {
        float s0 = 1.0f / (1.0f + expf(-p0));
        float s1 = 1.0f / (1.0f + expf(-p1));
        if (has_r1) {
            *(float2*)(out + r0) = make_float2(s0, s1);  // r0 even -> 8B aligned
        } else {
            out[r0] = s0;
        }
    }
}

extern "C" void kernel_launch(void* const* d_in, const int* in_sizes, int n_in,
                              void* d_out, int out_size)
{
    const int*   x        = (const int*)  d_in[0];
    const float* tgt_base = (const float*)d_in[1];
    const float* tgt_a    = (const float*)d_in[2];
    const float* tgt_b    = (const float*)d_in[3];
    const float* ctx_base = (const float*)d_in[4];
    const float* ctx_a    = (const float*)d_in[5];
    const float* ctx_b    = (const float*)d_in[6];
    const float* tgt_w    = (const float*)d_in[7];
    const float* ctx_w    = (const float*)d_in[8];
    float* out = (float*)d_out;

    const int bs = in_sizes[0] / 3;
    const int rows_per_warp = 2;
    const int threads = 256;
    const int warps_per_block = threads / 32;
    const int rows_per_block = warps_per_block * rows_per_warp;
    const int blocks = (bs + rows_per_block - 1) / rows_per_block;

    sgns_kernel2<<<blocks, threads>>>(x, tgt_base, tgt_a, tgt_b,
                                      ctx_base, ctx_a, ctx_b,
                                      tgt_w, ctx_w, out, bs);
}